// round 13
// baseline (speedup 1.0000x reference)
#include <cuda_runtime.h>
#include <cuda_fp16.h>
#include <cstdint>
#include <math.h>

#define BATCH 4
#define SEQ   2048
#define DIM   768
#define HEADS 16
#define HDIM  48

// log2(e) / sqrt(48): folds softmax scale + exp2 conversion into Q
#define QSCALE 0.2082351f

// Scratch (static device globals allowed; runtime allocation is not)
__device__ __align__(128) __half g_xh[BATCH * SEQ * DIM];            // x in fp16
__device__ __align__(128) __half g_wh[4 * DIM * DIM];                // Wq,Wk,Wv,Wo fp16
__device__ __align__(128) __half g_q[BATCH * HEADS * SEQ * HDIM];    // [bh][s][d], pre-scaled
__device__ __align__(128) __half g_k[BATCH * HEADS * SEQ * HDIM];    // [bh][s][d]
__device__ __align__(128) __half g_vt[BATCH * HEADS * HDIM * SEQ];   // [bh][d][s] (transposed)
__device__ __align__(128) __half g_attn_h[BATCH * SEQ * DIM];        // [b][s][h*48+d] fp16

// ---------------------------------------------------------------------------
__device__ __forceinline__ uint32_t smem_u32(const void* p) {
    uint32_t a;
    asm("{ .reg .u64 t; cvta.to.shared.u64 t, %1; cvt.u32.u64 %0, t; }" : "=r"(a) : "l"(p));
    return a;
}
__device__ __forceinline__ void cp_async16(uint32_t saddr, const void* gptr) {
    asm volatile("cp.async.cg.shared.global [%0], [%1], 16;" :: "r"(saddr), "l"(gptr));
}
__device__ __forceinline__ void cp_commit() { asm volatile("cp.async.commit_group;" ::: "memory"); }
template <int N>
__device__ __forceinline__ void cp_wait() { asm volatile("cp.async.wait_group %0;" :: "n"(N) : "memory"); }

__device__ __forceinline__ void mma_f16(float* d, const uint32_t* a, const uint32_t* b) {
    asm volatile(
        "mma.sync.aligned.m16n8k16.row.col.f32.f16.f16.f32 "
        "{%0,%1,%2,%3}, {%4,%5,%6,%7}, {%8,%9}, {%0,%1,%2,%3};"
        : "+f"(d[0]), "+f"(d[1]), "+f"(d[2]), "+f"(d[3])
        : "r"(a[0]), "r"(a[1]), "r"(a[2]), "r"(a[3]), "r"(b[0]), "r"(b[1]));
}
// fp16-accumulator mma: d/c are 2 x f16x2 regs
__device__ __forceinline__ void mma_f16acc(uint32_t* d, const uint32_t* a, const uint32_t* b) {
    asm volatile(
        "mma.sync.aligned.m16n8k16.row.col.f16.f16.f16.f16 "
        "{%0,%1}, {%2,%3,%4,%5}, {%6,%7}, {%0,%1};"
        : "+r"(d[0]), "+r"(d[1])
        : "r"(a[0]), "r"(a[1]), "r"(a[2]), "r"(a[3]), "r"(b[0]), "r"(b[1]));
}
__device__ __forceinline__ void ldsm_x4(uint32_t* r, uint32_t addr) {
    asm volatile("ldmatrix.sync.aligned.m8n8.x4.shared.b16 {%0,%1,%2,%3}, [%4];"
        : "=r"(r[0]), "=r"(r[1]), "=r"(r[2]), "=r"(r[3]) : "r"(addr));
}
__device__ __forceinline__ uint32_t pack_h2(float lo, float hi) {
    uint32_t r; asm("cvt.rn.f16x2.f32 %0, %1, %2;" : "=r"(r) : "f"(hi), "f"(lo)); return r;
}
__device__ __forceinline__ uint32_t h2ex2(uint32_t x) {
    uint32_t r; asm("ex2.approx.f16x2 %0, %1;" : "=r"(r) : "r"(x)); return r;
}

// ===========================================================================
// fp32 -> fp16 conversion of x and the 4 weight matrices (one pass)
// ===========================================================================
#define X_F4   ((BATCH * SEQ * DIM) / 4)
#define W_F4   ((DIM * DIM) / 4)
#define TOT_F4 (X_F4 + 4 * W_F4)

__global__ __launch_bounds__(256)
void cvt_kernel(const float* __restrict__ x,  const float* __restrict__ wq,
                const float* __restrict__ wk, const float* __restrict__ wv,
                const float* __restrict__ wo)
{
    size_t i = (size_t)blockIdx.x * blockDim.x + threadIdx.x;
    if (i >= TOT_F4) return;
    const float* src;
    __half* dst;
    size_t off;
    if (i < X_F4) {
        src = x; dst = g_xh; off = i;
    } else {
        size_t j = i - X_F4;
        int w = (int)(j / W_F4);
        off = j % W_F4;
        src = (w == 0) ? wq : (w == 1) ? wk : (w == 2) ? wv : wo;
        dst = g_wh + (size_t)w * (DIM * DIM);
    }
    float4 v = ((const float4*)src)[off];
    __half2* d2 = (__half2*)(dst + off * 4);
    d2[0] = __floats2half2_rn(v.x, v.y);
    d2[1] = __floats2half2_rn(v.z, v.w);
}

// ===========================================================================
// fp16 mma.sync GEMM (exact R11 config: 128x64 CTA, 256 thr, 2 CTAs/SM,
// 3-stage cp.async pipeline).
// ===========================================================================
#define FKT 64
#define NFKT (DIM / FKT)           // 12
#define FST 72                     // halves per row (144 B)
#define HTA (128 * FST)
#define HTB (64 * FST)
#define FSTAGE (HTA + HTB)
#define FSMEM_BYTES (3 * FSTAGE * 2)   // 82944 B

__global__ __launch_bounds__(256, 2)
void gemm_h(const __half* __restrict__ A, const __half* __restrict__ Wbase,
            const float* __restrict__ bias0, const float* __restrict__ bias1,
            const float* __restrict__ bias2, float* __restrict__ Cout, int fused)
{
    extern __shared__ __half smh[];

    int widx, n0, out_mode;
    const __half* W;
    const float* bias;
    if (fused) {
        widx = blockIdx.x / 12;
        n0 = (blockIdx.x % 12) * 64;
        W = Wbase + (size_t)widx * (DIM * DIM);
        bias = (widx == 0) ? bias0 : (widx == 1) ? bias1 : bias2;
        out_mode = 1 + widx;
    } else {
        n0 = blockIdx.x * 64;
        W = Wbase;
        bias = bias0;
        out_mode = 0;
    }
    const int m0 = blockIdx.y * 128;

    const int tid  = threadIdx.x;
    const int wi   = tid >> 5;
    const int lane = tid & 31;
    const int wm = (wi & 3) * 32;
    const int wn = (wi >> 2) * 32;
    const int grp = lane >> 2;
    const int tig = lane & 3;
    const int lr = lane & 7;
    const int g  = lane >> 3;

    uint32_t aoff[2], boff[2];
#pragma unroll
    for (int mt = 0; mt < 2; mt++)
        aoff[mt] = (uint32_t)((wm + mt * 16 + (g & 1) * 8 + lr) * 144 + (g >> 1) * 16);
#pragma unroll
    for (int p = 0; p < 2; p++)
        boff[p] = (uint32_t)((wn + p * 16 + (g >> 1) * 8 + lr) * 144 + (g & 1) * 16);

    float acc[8][4];
#pragma unroll
    for (int i = 0; i < 8; i++)
#pragma unroll
        for (int j = 0; j < 4; j++) acc[i][j] = 0.f;

    const uint32_t sbase = smem_u32(smh);

    auto load_tile = [&](int j, int st) {
        const int k0 = j * FKT;
        const uint32_t da = sbase + st * (FSTAGE * 2);
        const uint32_t db = da + HTA * 2;
#pragma unroll
        for (int i = 0; i < 4; i++) {
            int idx = tid + i * 256;
            int r = idx >> 3, c = idx & 7;
            cp_async16(da + r * 144 + c * 16, A + (size_t)(m0 + r) * DIM + k0 + c * 8);
        }
#pragma unroll
        for (int i = 0; i < 2; i++) {
            int idx = tid + i * 256;
            int r = idx >> 3, c = idx & 7;
            cp_async16(db + r * 144 + c * 16, W + (size_t)(n0 + r) * DIM + k0 + c * 8);
        }
    };

    load_tile(0, 0); cp_commit();
    load_tile(1, 1); cp_commit();

    for (int kt = 0; kt < NFKT; kt++) {
        const int s = kt % 3;
        if (kt == NFKT - 1) cp_wait<0>(); else cp_wait<1>();
        __syncthreads();
        if (kt + 2 < NFKT) {
            load_tile(kt + 2, (kt + 2) % 3);
            cp_commit();
        }

        const uint32_t aB = sbase + s * (FSTAGE * 2);
        const uint32_t bB = aB + HTA * 2;
#pragma unroll
        for (int ks = 0; ks < 4; ks++) {
            const uint32_t kb = ks * 32;
            uint32_t a[2][4], b[2][4];
            ldsm_x4(a[0], aB + aoff[0] + kb);
            ldsm_x4(a[1], aB + aoff[1] + kb);
            ldsm_x4(b[0], bB + boff[0] + kb);
            ldsm_x4(b[1], bB + boff[1] + kb);
#pragma unroll
            for (int mt = 0; mt < 2; mt++) {
                mma_f16(acc[mt * 4 + 0], a[mt], &b[0][0]);
                mma_f16(acc[mt * 4 + 1], a[mt], &b[0][2]);
                mma_f16(acc[mt * 4 + 2], a[mt], &b[1][0]);
                mma_f16(acc[mt * 4 + 3], a[mt], &b[1][2]);
            }
        }
    }

#pragma unroll
    for (int mt = 0; mt < 2; mt++) {
#pragma unroll
        for (int nt = 0; nt < 4; nt++) {
            const float* d = acc[mt * 4 + nt];
            int r0 = m0 + wm + mt * 16 + grp;
            int c0 = n0 + wn + nt * 8 + tig * 2;
#pragma unroll
            for (int e = 0; e < 4; e++) {
                int row = r0 + (e >> 1) * 8;
                int col = c0 + (e & 1);
                float v = d[e] + bias[col];
                if (out_mode == 0) {
                    Cout[(size_t)row * DIM + col] = v;
                } else {
                    int b2 = row >> 11;
                    int s2 = row & 2047;
                    int h = col / HDIM;
                    int dd = col - h * HDIM;
                    size_t bh = (size_t)b2 * HEADS + h;
                    if (out_mode == 1)
                        g_q[(bh * SEQ + s2) * HDIM + dd] = __float2half(v * QSCALE);
                    else if (out_mode == 2)
                        g_k[(bh * SEQ + s2) * HDIM + dd] = __float2half(v);
                    else
                        g_vt[(bh * HDIM + dd) * SEQ + s2] = __float2half(v);
                }
            }
        }
    }
}

// ===========================================================================
// Flash attention: ABQ=64 CTAs (fine-grained for wave packing), 4 warps x
// 16 rows, 5 CTAs/SM. f16-accum S-phase -> direct exp2; PV + l fp32 accum.
// 2-stage KV cp.async pipeline, dynamic smem.
// ===========================================================================
#define ABQ 64
#define ABK 64
#define NKV (SEQ / ABK)            // 32
#define AQ_BYTES   (ABQ * 112)                  // 7168
#define AK_BYTES   (ABK * 112)                  // 7168
#define AV_BYTES   (HDIM * 144)                 // 6912
#define AKV_STAGE  (AK_BYTES + AV_BYTES)        // 14080
#define ASMEM_BYTES (AQ_BYTES + 2 * AKV_STAGE)  // 35328

__global__ __launch_bounds__(128, 5)
void attn_mma()
{
    extern __shared__ char asmem[];
    const uint32_t sbase = smem_u32(asmem);

    const int qt  = blockIdx.x;
    const int bh  = blockIdx.y;
    const int tid = threadIdx.x;
    const int w    = tid >> 5;
    const int lane = tid & 31;
    const int grp = lane >> 2, tig = lane & 3;
    const int lr = lane & 7;
    const int g  = lane >> 3;

    const __half* Qg = g_q  + ((size_t)bh * SEQ + qt * ABQ) * HDIM;
    const __half* Kg = g_k  + (size_t)bh * SEQ * HDIM;
    const __half* Vg = g_vt + (size_t)bh * HDIM * SEQ;

    auto load_kv = [&](int kt, int st) {
        const char* kg = (const char*)(Kg + (size_t)kt * ABK * HDIM);
        const uint32_t kdst = sbase + AQ_BYTES + st * AKV_STAGE;
        for (int i = tid; i < 384; i += 128) {           // 64 rows x 6 chunks
            int r = i / 6, c = i % 6;
            cp_async16(kdst + r * 112 + c * 16, kg + r * 96 + c * 16);
        }
        const char* vg = (const char*)(Vg + kt * ABK);
        const uint32_t vdst = kdst + AK_BYTES;
        for (int i = tid; i < 384; i += 128) {           // 48 rows x 8 chunks
            int d = i / 8, c = i % 8;
            cp_async16(vdst + d * 144 + c * 16, vg + (size_t)d * SEQ * 2 + c * 16);
        }
    };

    {   // Q tile: 64 rows x 6 chunks
        for (int i = tid; i < 384; i += 128) {
            int r = i / 6, c = i % 6;
            cp_async16(sbase + r * 112 + c * 16, (const char*)Qg + r * 96 + c * 16);
        }
    }
    load_kv(0, 0);
    cp_commit();

    const uint32_t qoff = (uint32_t)((w * 16 + (g & 1) * 8 + lr) * 112 + (g >> 1) * 16);
    uint32_t koff[4], voff[3];
#pragma unroll
    for (int j = 0; j < 4; j++)
        koff[j] = (uint32_t)((j * 16 + (g >> 1) * 8 + lr) * 112 + (g & 1) * 16);
#pragma unroll
    for (int j = 0; j < 3; j++)
        voff[j] = (uint32_t)((j * 16 + (g >> 1) * 8 + lr) * 144 + (g & 1) * 16);

    // constant B-fragment: virtual ones column
    uint32_t bones[2];
    bones[0] = bones[1] = (grp == 0) ? 0x3C003C00u : 0u;

    uint32_t qf[3][4];
    float o[6][4];
    float ol[4];
#pragma unroll
    for (int i = 0; i < 6; i++)
#pragma unroll
        for (int j = 0; j < 4; j++) o[i][j] = 0.f;
#pragma unroll
    for (int j = 0; j < 4; j++) ol[j] = 0.f;

    for (int kt = 0; kt < NKV; kt++) {
        const int s = kt & 1;
        if (kt + 1 < NKV) {
            load_kv(kt + 1, s ^ 1);
            cp_commit();
            cp_wait<1>();
        } else {
            cp_wait<0>();
        }
        __syncthreads();

        if (kt == 0) {
#pragma unroll
            for (int ks = 0; ks < 3; ks++)
                ldsm_x4(qf[ks], sbase + qoff + ks * 32);
        }

        // ---- S = Q K^T in fp16 accumulators -> direct exp2 -> P frags ----
        uint32_t pf[4][4];
        const uint32_t kB = sbase + AQ_BYTES + s * AKV_STAGE;
#pragma unroll
        for (int j = 0; j < 4; j++) {
            uint32_t b[3][4];
            ldsm_x4(b[0], kB + koff[j]);
            ldsm_x4(b[1], kB + koff[j] + 32);
            ldsm_x4(b[2], kB + koff[j] + 64);
            uint32_t s0[2] = {0u, 0u};
            uint32_t s1[2] = {0u, 0u};
#pragma unroll
            for (int ks = 0; ks < 3; ks++) {
                mma_f16acc(s0, qf[ks], &b[ks][0]);
                mma_f16acc(s1, qf[ks], &b[ks][2]);
            }
            pf[j][0] = h2ex2(s0[0]);
            pf[j][1] = h2ex2(s0[1]);
            pf[j][2] = h2ex2(s1[0]);
            pf[j][3] = h2ex2(s1[1]);
        }

        // ---- O += P V ; l += P @ ones (fp32 accum) ----
        const uint32_t vB = kB + AK_BYTES;
#pragma unroll
        for (int j = 0; j < 3; j++) {
            uint32_t b[4][4];
            ldsm_x4(b[0], vB + voff[j]);
            ldsm_x4(b[1], vB + voff[j] + 32);
            ldsm_x4(b[2], vB + voff[j] + 64);
            ldsm_x4(b[3], vB + voff[j] + 96);
#pragma unroll
            for (int ks = 0; ks < 4; ks++) {
                mma_f16(o[2 * j],     pf[ks], &b[ks][0]);
                mma_f16(o[2 * j + 1], pf[ks], &b[ks][2]);
            }
        }
#pragma unroll
        for (int ks = 0; ks < 4; ks++)
            mma_f16(ol, pf[ks], bones);

        __syncthreads();
    }

    // ---- epilogue ----
    const int b2 = bh >> 4, h = bh & 15;
    float l0 = __shfl_sync(0xffffffffu, ol[0], lane & 28);
    float l1 = __shfl_sync(0xffffffffu, ol[2], lane & 28);
    const float i0 = 1.f / l0, i1 = 1.f / l1;
    const int r0 = qt * ABQ + w * 16 + grp;
#pragma unroll
    for (int nt = 0; nt < 6; nt++) {
        int col = h * HDIM + nt * 8 + 2 * tig;
        uint32_t p0 = pack_h2(o[nt][0] * i0, o[nt][1] * i0);
        uint32_t p1 = pack_h2(o[nt][2] * i1, o[nt][3] * i1);
        *(uint32_t*)&g_attn_h[((size_t)b2 * SEQ + r0) * DIM + col] = p0;
        *(uint32_t*)&g_attn_h[((size_t)b2 * SEQ + r0 + 8) * DIM + col] = p1;
    }
}

// ---------------------------------------------------------------------------
extern "C" void kernel_launch(void* const* d_in, const int* in_sizes, int n_in,
                              void* d_out, int out_size)
{
    const float* x  = (const float*)d_in[0];
    const float* Wq = (const float*)d_in[1];
    const float* bq = (const float*)d_in[2];
    const float* Wk = (const float*)d_in[3];
    const float* bk = (const float*)d_in[4];
    const float* Wv = (const float*)d_in[5];
    const float* bv = (const float*)d_in[6];
    const float* Wo = (const float*)d_in[7];
    const float* bo = (const float*)d_in[8];
    float* out = (float*)d_out;

    cudaFuncSetAttribute(gemm_h, cudaFuncAttributeMaxDynamicSharedMemorySize, FSMEM_BYTES);
    cudaFuncSetAttribute(attn_mma, cudaFuncAttributeMaxDynamicSharedMemorySize, ASMEM_BYTES);

    cvt_kernel<<<(TOT_F4 + 255) / 256, 256>>>(x, Wq, Wk, Wv, Wo);

    __half* xh = nullptr; __half* wh = nullptr; __half* ah = nullptr;
    cudaGetSymbolAddress((void**)&xh, g_xh);
    cudaGetSymbolAddress((void**)&wh, g_wh);
    cudaGetSymbolAddress((void**)&ah, g_attn_h);

    dim3 qkv_grid(36, (BATCH * SEQ) / 128);
    gemm_h<<<qkv_grid, 256, FSMEM_BYTES>>>(xh, wh, bq, bk, bv, nullptr, 1);

    dim3 agrid(SEQ / ABQ, HEADS * BATCH);  // (32, 64)
    attn_mma<<<agrid, 128, ASMEM_BYTES>>>();

    dim3 o_grid(12, (BATCH * SEQ) / 128);
    gemm_h<<<o_grid, 256, FSMEM_BYTES>>>(ah, wh + 3 * DIM * DIM, bo, nullptr, nullptr, out, 0);
}

// round 14
// speedup vs baseline: 1.0083x; 1.0083x over previous
#include <cuda_runtime.h>
#include <cuda_fp16.h>
#include <cstdint>
#include <math.h>

#define BATCH 4
#define SEQ   2048
#define DIM   768
#define HEADS 16
#define HDIM  48

// log2(e) / sqrt(48): folds softmax scale + exp2 conversion into Q
#define QSCALE 0.2082351f

// Scratch (static device globals allowed; runtime allocation is not)
__device__ __align__(128) __half g_xh[BATCH * SEQ * DIM];            // x in fp16
__device__ __align__(128) __half g_wh[4 * DIM * DIM];                // Wq,Wk,Wv,Wo fp16
__device__ __align__(128) __half g_q[BATCH * HEADS * SEQ * HDIM];    // [bh][s][d], pre-scaled
__device__ __align__(128) __half g_k[BATCH * HEADS * SEQ * HDIM];    // [bh][s][d]
__device__ __align__(128) __half g_vt[BATCH * HEADS * HDIM * SEQ];   // [bh][d][s] (transposed)
__device__ __align__(128) __half g_attn_h[BATCH * SEQ * DIM];        // [b][s][h*48+d] fp16

// ---------------------------------------------------------------------------
__device__ __forceinline__ uint32_t smem_u32(const void* p) {
    uint32_t a;
    asm("{ .reg .u64 t; cvta.to.shared.u64 t, %1; cvt.u32.u64 %0, t; }" : "=r"(a) : "l"(p));
    return a;
}
__device__ __forceinline__ void cp_async16(uint32_t saddr, const void* gptr) {
    asm volatile("cp.async.cg.shared.global [%0], [%1], 16;" :: "r"(saddr), "l"(gptr));
}
__device__ __forceinline__ void cp_commit() { asm volatile("cp.async.commit_group;" ::: "memory"); }
template <int N>
__device__ __forceinline__ void cp_wait() { asm volatile("cp.async.wait_group %0;" :: "n"(N) : "memory"); }

__device__ __forceinline__ void mma_f16(float* d, const uint32_t* a, const uint32_t* b) {
    asm volatile(
        "mma.sync.aligned.m16n8k16.row.col.f32.f16.f16.f32 "
        "{%0,%1,%2,%3}, {%4,%5,%6,%7}, {%8,%9}, {%0,%1,%2,%3};"
        : "+f"(d[0]), "+f"(d[1]), "+f"(d[2]), "+f"(d[3])
        : "r"(a[0]), "r"(a[1]), "r"(a[2]), "r"(a[3]), "r"(b[0]), "r"(b[1]));
}
// fp16-accumulator mma: d/c are 2 x f16x2 regs
__device__ __forceinline__ void mma_f16acc(uint32_t* d, const uint32_t* a, const uint32_t* b) {
    asm volatile(
        "mma.sync.aligned.m16n8k16.row.col.f16.f16.f16.f16 "
        "{%0,%1}, {%2,%3,%4,%5}, {%6,%7}, {%0,%1};"
        : "+r"(d[0]), "+r"(d[1])
        : "r"(a[0]), "r"(a[1]), "r"(a[2]), "r"(a[3]), "r"(b[0]), "r"(b[1]));
}
__device__ __forceinline__ void ldsm_x4(uint32_t* r, uint32_t addr) {
    asm volatile("ldmatrix.sync.aligned.m8n8.x4.shared.b16 {%0,%1,%2,%3}, [%4];"
        : "=r"(r[0]), "=r"(r[1]), "=r"(r[2]), "=r"(r[3]) : "r"(addr));
}
__device__ __forceinline__ uint32_t pack_h2(float lo, float hi) {
    uint32_t r; asm("cvt.rn.f16x2.f32 %0, %1, %2;" : "=r"(r) : "f"(hi), "f"(lo)); return r;
}
__device__ __forceinline__ uint32_t h2ex2(uint32_t x) {
    uint32_t r; asm("ex2.approx.f16x2 %0, %1;" : "=r"(r) : "r"(x)); return r;
}

// ===========================================================================
// fp32 -> fp16 conversion of x and the 4 weight matrices (one pass)
// ===========================================================================
#define X_F4   ((BATCH * SEQ * DIM) / 4)
#define W_F4   ((DIM * DIM) / 4)
#define TOT_F4 (X_F4 + 4 * W_F4)

__global__ __launch_bounds__(256)
void cvt_kernel(const float* __restrict__ x,  const float* __restrict__ wq,
                const float* __restrict__ wk, const float* __restrict__ wv,
                const float* __restrict__ wo)
{
    size_t i = (size_t)blockIdx.x * blockDim.x + threadIdx.x;
    if (i >= TOT_F4) return;
    const float* src;
    __half* dst;
    size_t off;
    if (i < X_F4) {
        src = x; dst = g_xh; off = i;
    } else {
        size_t j = i - X_F4;
        int w = (int)(j / W_F4);
        off = j % W_F4;
        src = (w == 0) ? wq : (w == 1) ? wk : (w == 2) ? wv : wo;
        dst = g_wh + (size_t)w * (DIM * DIM);
    }
    float4 v = ((const float4*)src)[off];
    __half2* d2 = (__half2*)(dst + off * 4);
    d2[0] = __floats2half2_rn(v.x, v.y);
    d2[1] = __floats2half2_rn(v.z, v.w);
}

// ===========================================================================
// fp16 mma.sync GEMM: 128x64 CTA, 256 thr, 2-stage pipeline, 3 CTAs/SM
// (reg cap 85 via launch_bounds). One barrier per k-iteration.
// ===========================================================================
#define FKT 64
#define NFKT (DIM / FKT)           // 12
#define FST 72                     // halves per row (144 B)
#define HTA (128 * FST)
#define HTB (64 * FST)
#define FSTAGE (HTA + HTB)
#define FSMEM_BYTES (2 * FSTAGE * 2)   // 55296 B

__global__ __launch_bounds__(256, 3)
void gemm_h(const __half* __restrict__ A, const __half* __restrict__ Wbase,
            const float* __restrict__ bias0, const float* __restrict__ bias1,
            const float* __restrict__ bias2, float* __restrict__ Cout, int fused)
{
    extern __shared__ __half smh[];

    int widx, n0, out_mode;
    const __half* W;
    const float* bias;
    if (fused) {
        widx = blockIdx.x / 12;
        n0 = (blockIdx.x % 12) * 64;
        W = Wbase + (size_t)widx * (DIM * DIM);
        bias = (widx == 0) ? bias0 : (widx == 1) ? bias1 : bias2;
        out_mode = 1 + widx;
    } else {
        n0 = blockIdx.x * 64;
        W = Wbase;
        bias = bias0;
        out_mode = 0;
    }
    const int m0 = blockIdx.y * 128;

    const int tid  = threadIdx.x;
    const int wi   = tid >> 5;
    const int lane = tid & 31;
    const int wm = (wi & 3) * 32;
    const int wn = (wi >> 2) * 32;
    const int grp = lane >> 2;
    const int tig = lane & 3;
    const int lr = lane & 7;
    const int g  = lane >> 3;

    uint32_t aoff[2], boff[2];
#pragma unroll
    for (int mt = 0; mt < 2; mt++)
        aoff[mt] = (uint32_t)((wm + mt * 16 + (g & 1) * 8 + lr) * 144 + (g >> 1) * 16);
#pragma unroll
    for (int p = 0; p < 2; p++)
        boff[p] = (uint32_t)((wn + p * 16 + (g >> 1) * 8 + lr) * 144 + (g & 1) * 16);

    float acc[8][4];
#pragma unroll
    for (int i = 0; i < 8; i++)
#pragma unroll
        for (int j = 0; j < 4; j++) acc[i][j] = 0.f;

    const uint32_t sbase = smem_u32(smh);

    auto load_tile = [&](int j, int st) {
        const int k0 = j * FKT;
        const uint32_t da = sbase + st * (FSTAGE * 2);
        const uint32_t db = da + HTA * 2;
#pragma unroll
        for (int i = 0; i < 4; i++) {
            int idx = tid + i * 256;
            int r = idx >> 3, c = idx & 7;
            cp_async16(da + r * 144 + c * 16, A + (size_t)(m0 + r) * DIM + k0 + c * 8);
        }
#pragma unroll
        for (int i = 0; i < 2; i++) {
            int idx = tid + i * 256;
            int r = idx >> 3, c = idx & 7;
            cp_async16(db + r * 144 + c * 16, W + (size_t)(n0 + r) * DIM + k0 + c * 8);
        }
    };

    load_tile(0, 0); cp_commit();

    for (int kt = 0; kt < NFKT; kt++) {
        const int s = kt & 1;
        if (kt == NFKT - 1) cp_wait<0>(); else cp_wait<0>();  // tile kt landed
        __syncthreads();  // all warps done computing tile kt-1 (stage s^1)
        if (kt + 1 < NFKT) {
            load_tile(kt + 1, s ^ 1);
            cp_commit();
        }

        const uint32_t aB = sbase + s * (FSTAGE * 2);
        const uint32_t bB = aB + HTA * 2;
#pragma unroll
        for (int ks = 0; ks < 4; ks++) {
            const uint32_t kb = ks * 32;
            uint32_t a[2][4], b[2][4];
            ldsm_x4(a[0], aB + aoff[0] + kb);
            ldsm_x4(a[1], aB + aoff[1] + kb);
            ldsm_x4(b[0], bB + boff[0] + kb);
            ldsm_x4(b[1], bB + boff[1] + kb);
#pragma unroll
            for (int mt = 0; mt < 2; mt++) {
                mma_f16(acc[mt * 4 + 0], a[mt], &b[0][0]);
                mma_f16(acc[mt * 4 + 1], a[mt], &b[0][2]);
                mma_f16(acc[mt * 4 + 2], a[mt], &b[1][0]);
                mma_f16(acc[mt * 4 + 3], a[mt], &b[1][2]);
            }
        }
    }

#pragma unroll
    for (int mt = 0; mt < 2; mt++) {
#pragma unroll
        for (int nt = 0; nt < 4; nt++) {
            const float* d = acc[mt * 4 + nt];
            int r0 = m0 + wm + mt * 16 + grp;
            int c0 = n0 + wn + nt * 8 + tig * 2;
#pragma unroll
            for (int e = 0; e < 4; e++) {
                int row = r0 + (e >> 1) * 8;
                int col = c0 + (e & 1);
                float v = d[e] + bias[col];
                if (out_mode == 0) {
                    Cout[(size_t)row * DIM + col] = v;
                } else {
                    int b2 = row >> 11;
                    int s2 = row & 2047;
                    int h = col / HDIM;
                    int dd = col - h * HDIM;
                    size_t bh = (size_t)b2 * HEADS + h;
                    if (out_mode == 1)
                        g_q[(bh * SEQ + s2) * HDIM + dd] = __float2half(v * QSCALE);
                    else if (out_mode == 2)
                        g_k[(bh * SEQ + s2) * HDIM + dd] = __float2half(v);
                    else
                        g_vt[(bh * HDIM + dd) * SEQ + s2] = __float2half(v);
                }
            }
        }
    }
}

// ===========================================================================
// Flash attention (exact R11 config): S-phase fp16 accum -> direct exp2,
// PV + l fp32 accum, 3-stage KV pipeline, 128q CTA, 4 warps x 32 rows,
// 3 CTAs/SM.
// ===========================================================================
#define ABQ 128
#define ABK 64
#define NKV (SEQ / ABK)            // 32
#define AQ_BYTES   (ABQ * 112)                  // 14336
#define AK_BYTES   (ABK * 112)                  // 7168
#define AV_BYTES   (HDIM * 144)                 // 6912
#define AKV_STAGE  (AK_BYTES + AV_BYTES)        // 14080
#define ASMEM_BYTES (AQ_BYTES + 3 * AKV_STAGE)  // 56576

__global__ __launch_bounds__(128, 3)
void attn_mma()
{
    extern __shared__ char asmem[];
    const uint32_t sbase = smem_u32(asmem);

    const int qt  = blockIdx.x;
    const int bh  = blockIdx.y;
    const int tid = threadIdx.x;
    const int w    = tid >> 5;
    const int lane = tid & 31;
    const int grp = lane >> 2, tig = lane & 3;
    const int lr = lane & 7;
    const int g  = lane >> 3;

    const __half* Qg = g_q  + ((size_t)bh * SEQ + qt * ABQ) * HDIM;
    const __half* Kg = g_k  + (size_t)bh * SEQ * HDIM;
    const __half* Vg = g_vt + (size_t)bh * HDIM * SEQ;

    auto load_kv = [&](int kt, int st) {
        const char* kg = (const char*)(Kg + (size_t)kt * ABK * HDIM);
        const uint32_t kdst = sbase + AQ_BYTES + st * AKV_STAGE;
        for (int i = tid; i < 384; i += 128) {
            int r = i / 6, c = i % 6;
            cp_async16(kdst + r * 112 + c * 16, kg + r * 96 + c * 16);
        }
        const char* vg = (const char*)(Vg + kt * ABK);
        const uint32_t vdst = kdst + AK_BYTES;
        for (int i = tid; i < 384; i += 128) {
            int d = i / 8, c = i % 8;
            cp_async16(vdst + d * 144 + c * 16, vg + (size_t)d * SEQ * 2 + c * 16);
        }
    };

    {   // Q tile: 128 rows x 6 chunks
        for (int i = tid; i < 768; i += 128) {
            int r = i / 6, c = i % 6;
            cp_async16(sbase + r * 112 + c * 16, (const char*)Qg + r * 96 + c * 16);
        }
    }
    load_kv(0, 0); cp_commit();
    load_kv(1, 1); cp_commit();

    uint32_t qoff[2];
#pragma unroll
    for (int blk = 0; blk < 2; blk++)
        qoff[blk] = (uint32_t)((w * 32 + blk * 16 + (g & 1) * 8 + lr) * 112 + (g >> 1) * 16);
    uint32_t koff[4], voff[3];
#pragma unroll
    for (int j = 0; j < 4; j++)
        koff[j] = (uint32_t)((j * 16 + (g >> 1) * 8 + lr) * 112 + (g & 1) * 16);
#pragma unroll
    for (int j = 0; j < 3; j++)
        voff[j] = (uint32_t)((j * 16 + (g >> 1) * 8 + lr) * 144 + (g & 1) * 16);

    // constant B-fragment: virtual ones column
    uint32_t bones[2];
    bones[0] = bones[1] = (grp == 0) ? 0x3C003C00u : 0u;

    uint32_t qf[2][3][4];
    float o[2][6][4];
    float ol[2][4];
#pragma unroll
    for (int blk = 0; blk < 2; blk++) {
#pragma unroll
        for (int i = 0; i < 6; i++)
#pragma unroll
            for (int j = 0; j < 4; j++) o[blk][i][j] = 0.f;
#pragma unroll
        for (int j = 0; j < 4; j++) ol[blk][j] = 0.f;
    }

    for (int kt = 0; kt < NKV; kt++) {
        const int s = kt % 3;
        if (kt == NKV - 1) cp_wait<0>(); else cp_wait<1>();
        __syncthreads();
        if (kt + 2 < NKV) {
            load_kv(kt + 2, (kt + 2) % 3);
            cp_commit();
        }

        if (kt == 0) {
#pragma unroll
            for (int blk = 0; blk < 2; blk++)
#pragma unroll
                for (int ks = 0; ks < 3; ks++)
                    ldsm_x4(qf[blk][ks], sbase + qoff[blk] + ks * 32);
        }

        // ---- S = Q K^T in fp16 accumulators -> direct exp2 -> P frags ----
        uint32_t pf[2][4][4];
        const uint32_t kB = sbase + AQ_BYTES + s * AKV_STAGE;
#pragma unroll
        for (int j = 0; j < 4; j++) {
            uint32_t b[3][4];
            ldsm_x4(b[0], kB + koff[j]);
            ldsm_x4(b[1], kB + koff[j] + 32);
            ldsm_x4(b[2], kB + koff[j] + 64);
#pragma unroll
            for (int blk = 0; blk < 2; blk++) {
                uint32_t s0[2] = {0u, 0u};
                uint32_t s1[2] = {0u, 0u};
#pragma unroll
                for (int ks = 0; ks < 3; ks++) {
                    mma_f16acc(s0, qf[blk][ks], &b[ks][0]);
                    mma_f16acc(s1, qf[blk][ks], &b[ks][2]);
                }
                pf[blk][j][0] = h2ex2(s0[0]);
                pf[blk][j][1] = h2ex2(s0[1]);
                pf[blk][j][2] = h2ex2(s1[0]);
                pf[blk][j][3] = h2ex2(s1[1]);
            }
        }

        // ---- O += P V ; l += P @ ones (fp32 accum) ----
        const uint32_t vB = kB + AK_BYTES;
#pragma unroll
        for (int j = 0; j < 3; j++) {
            uint32_t b[4][4];
            ldsm_x4(b[0], vB + voff[j]);
            ldsm_x4(b[1], vB + voff[j] + 32);
            ldsm_x4(b[2], vB + voff[j] + 64);
            ldsm_x4(b[3], vB + voff[j] + 96);
#pragma unroll
            for (int blk = 0; blk < 2; blk++)
#pragma unroll
                for (int ks = 0; ks < 4; ks++) {
                    mma_f16(o[blk][2 * j],     pf[blk][ks], &b[ks][0]);
                    mma_f16(o[blk][2 * j + 1], pf[blk][ks], &b[ks][2]);
                }
        }
#pragma unroll
        for (int blk = 0; blk < 2; blk++)
#pragma unroll
            for (int ks = 0; ks < 4; ks++)
                mma_f16(ol[blk], pf[blk][ks], bones);
    }

    // ---- epilogue ----
    const int b2 = bh >> 4, h = bh & 15;
#pragma unroll
    for (int blk = 0; blk < 2; blk++) {
        float l0 = __shfl_sync(0xffffffffu, ol[blk][0], lane & 28);
        float l1 = __shfl_sync(0xffffffffu, ol[blk][2], lane & 28);
        const float i0 = 1.f / l0, i1 = 1.f / l1;
        const int r0 = qt * ABQ + w * 32 + blk * 16 + grp;
#pragma unroll
        for (int nt = 0; nt < 6; nt++) {
            int col = h * HDIM + nt * 8 + 2 * tig;
            uint32_t p0 = pack_h2(o[blk][nt][0] * i0, o[blk][nt][1] * i0);
            uint32_t p1 = pack_h2(o[blk][nt][2] * i1, o[blk][nt][3] * i1);
            *(uint32_t*)&g_attn_h[((size_t)b2 * SEQ + r0) * DIM + col] = p0;
            *(uint32_t*)&g_attn_h[((size_t)b2 * SEQ + r0 + 8) * DIM + col] = p1;
        }
    }
}

// ---------------------------------------------------------------------------
extern "C" void kernel_launch(void* const* d_in, const int* in_sizes, int n_in,
                              void* d_out, int out_size)
{
    const float* x  = (const float*)d_in[0];
    const float* Wq = (const float*)d_in[1];
    const float* bq = (const float*)d_in[2];
    const float* Wk = (const float*)d_in[3];
    const float* bk = (const float*)d_in[4];
    const float* Wv = (const float*)d_in[5];
    const float* bv = (const float*)d_in[6];
    const float* Wo = (const float*)d_in[7];
    const float* bo = (const float*)d_in[8];
    float* out = (float*)d_out;

    cudaFuncSetAttribute(gemm_h, cudaFuncAttributeMaxDynamicSharedMemorySize, FSMEM_BYTES);
    cudaFuncSetAttribute(attn_mma, cudaFuncAttributeMaxDynamicSharedMemorySize, ASMEM_BYTES);

    cvt_kernel<<<(TOT_F4 + 255) / 256, 256>>>(x, Wq, Wk, Wv, Wo);

    __half* xh = nullptr; __half* wh = nullptr; __half* ah = nullptr;
    cudaGetSymbolAddress((void**)&xh, g_xh);
    cudaGetSymbolAddress((void**)&wh, g_wh);
    cudaGetSymbolAddress((void**)&ah, g_attn_h);

    dim3 qkv_grid(36, (BATCH * SEQ) / 128);
    gemm_h<<<qkv_grid, 256, FSMEM_BYTES>>>(xh, wh, bq, bk, bv, nullptr, 1);

    dim3 agrid(SEQ / ABQ, HEADS * BATCH);  // (16, 64)
    attn_mma<<<agrid, 128, ASMEM_BYTES>>>();

    dim3 o_grid(12, (BATCH * SEQ) / 128);
    gemm_h<<<o_grid, 256, FSMEM_BYTES>>>(ah, wh + 3 * DIM * DIM, bo, nullptr, nullptr, out, 0);
}

// round 15
// speedup vs baseline: 1.0865x; 1.0775x over previous
#include <cuda_runtime.h>
#include <cuda_fp16.h>
#include <cstdint>
#include <math.h>

#define BATCH 4
#define SEQ   2048
#define DIM   768
#define HEADS 16
#define HDIM  48

// log2(e) / sqrt(48): folds softmax scale + exp2 conversion into Q
#define QSCALE 0.2082351f

// Scratch (static device globals allowed; runtime allocation is not)
__device__ __align__(128) __half g_xh[BATCH * SEQ * DIM];            // x in fp16
__device__ __align__(128) __half g_wh[4 * DIM * DIM];                // Wq,Wk,Wv,Wo fp16
__device__ __align__(128) __half g_q[BATCH * HEADS * SEQ * HDIM];    // [bh][s][d], pre-scaled
__device__ __align__(128) __half g_k[BATCH * HEADS * SEQ * HDIM];    // [bh][s][d]
__device__ __align__(128) __half g_vt[BATCH * HEADS * HDIM * SEQ];   // [bh][d][s] (transposed)
__device__ __align__(128) __half g_attn_h[BATCH * SEQ * DIM];        // [b][s][h*48+d] fp16

// ---------------------------------------------------------------------------
__device__ __forceinline__ uint32_t smem_u32(const void* p) {
    uint32_t a;
    asm("{ .reg .u64 t; cvta.to.shared.u64 t, %1; cvt.u32.u64 %0, t; }" : "=r"(a) : "l"(p));
    return a;
}
__device__ __forceinline__ void cp_async16(uint32_t saddr, const void* gptr) {
    asm volatile("cp.async.cg.shared.global [%0], [%1], 16;" :: "r"(saddr), "l"(gptr));
}
__device__ __forceinline__ void cp_commit() { asm volatile("cp.async.commit_group;" ::: "memory"); }
template <int N>
__device__ __forceinline__ void cp_wait() { asm volatile("cp.async.wait_group %0;" :: "n"(N) : "memory"); }

__device__ __forceinline__ void mma_f16(float* d, const uint32_t* a, const uint32_t* b) {
    asm volatile(
        "mma.sync.aligned.m16n8k16.row.col.f32.f16.f16.f32 "
        "{%0,%1,%2,%3}, {%4,%5,%6,%7}, {%8,%9}, {%0,%1,%2,%3};"
        : "+f"(d[0]), "+f"(d[1]), "+f"(d[2]), "+f"(d[3])
        : "r"(a[0]), "r"(a[1]), "r"(a[2]), "r"(a[3]), "r"(b[0]), "r"(b[1]));
}
// fp16-accumulator mma: d/c are 2 x f16x2 regs
__device__ __forceinline__ void mma_f16acc(uint32_t* d, const uint32_t* a, const uint32_t* b) {
    asm volatile(
        "mma.sync.aligned.m16n8k16.row.col.f16.f16.f16.f16 "
        "{%0,%1}, {%2,%3,%4,%5}, {%6,%7}, {%0,%1};"
        : "+r"(d[0]), "+r"(d[1])
        : "r"(a[0]), "r"(a[1]), "r"(a[2]), "r"(a[3]), "r"(b[0]), "r"(b[1]));
}
__device__ __forceinline__ void ldsm_x4(uint32_t* r, uint32_t addr) {
    asm volatile("ldmatrix.sync.aligned.m8n8.x4.shared.b16 {%0,%1,%2,%3}, [%4];"
        : "=r"(r[0]), "=r"(r[1]), "=r"(r[2]), "=r"(r[3]) : "r"(addr));
}
__device__ __forceinline__ uint32_t pack_h2(float lo, float hi) {
    uint32_t r; asm("cvt.rn.f16x2.f32 %0, %1, %2;" : "=r"(r) : "f"(hi), "f"(lo)); return r;
}
__device__ __forceinline__ uint32_t h2ex2(uint32_t x) {
    uint32_t r; asm("ex2.approx.f16x2 %0, %1;" : "=r"(r) : "r"(x)); return r;
}

// ===========================================================================
// fp32 -> fp16 conversion of x and the 4 weight matrices (one pass)
// ===========================================================================
#define X_F4   ((BATCH * SEQ * DIM) / 4)
#define W_F4   ((DIM * DIM) / 4)
#define TOT_F4 (X_F4 + 4 * W_F4)

__global__ __launch_bounds__(256)
void cvt_kernel(const float* __restrict__ x,  const float* __restrict__ wq,
                const float* __restrict__ wk, const float* __restrict__ wv,
                const float* __restrict__ wo)
{
    size_t i = (size_t)blockIdx.x * blockDim.x + threadIdx.x;
    if (i >= TOT_F4) return;
    const float* src;
    __half* dst;
    size_t off;
    if (i < X_F4) {
        src = x; dst = g_xh; off = i;
    } else {
        size_t j = i - X_F4;
        int w = (int)(j / W_F4);
        off = j % W_F4;
        src = (w == 0) ? wq : (w == 1) ? wk : (w == 2) ? wv : wo;
        dst = g_wh + (size_t)w * (DIM * DIM);
    }
    float4 v = ((const float4*)src)[off];
    __half2* d2 = (__half2*)(dst + off * 4);
    d2[0] = __floats2half2_rn(v.x, v.y);
    d2[1] = __floats2half2_rn(v.z, v.w);
}

// ===========================================================================
// fp16 mma.sync GEMM (R11 champion config): 128x64 CTA, 256 thr, 2 CTAs/SM,
// 3-stage cp.async pipeline, one barrier per k-iter. Vectorized epilogue.
// ===========================================================================
#define FKT 64
#define NFKT (DIM / FKT)           // 12
#define FST 72                     // halves per row (144 B)
#define HTA (128 * FST)
#define HTB (64 * FST)
#define FSTAGE (HTA + HTB)
#define FSMEM_BYTES (3 * FSTAGE * 2)   // 82944 B

__global__ __launch_bounds__(256, 2)
void gemm_h(const __half* __restrict__ A, const __half* __restrict__ Wbase,
            const float* __restrict__ bias0, const float* __restrict__ bias1,
            const float* __restrict__ bias2, float* __restrict__ Cout, int fused)
{
    extern __shared__ __half smh[];

    int widx, n0, out_mode;
    const __half* W;
    const float* bias;
    if (fused) {
        widx = blockIdx.x / 12;
        n0 = (blockIdx.x % 12) * 64;
        W = Wbase + (size_t)widx * (DIM * DIM);
        bias = (widx == 0) ? bias0 : (widx == 1) ? bias1 : bias2;
        out_mode = 1 + widx;
    } else {
        n0 = blockIdx.x * 64;
        W = Wbase;
        bias = bias0;
        out_mode = 0;
    }
    const int m0 = blockIdx.y * 128;

    const int tid  = threadIdx.x;
    const int wi   = tid >> 5;
    const int lane = tid & 31;
    const int wm = (wi & 3) * 32;
    const int wn = (wi >> 2) * 32;
    const int grp = lane >> 2;
    const int tig = lane & 3;
    const int lr = lane & 7;
    const int g  = lane >> 3;

    uint32_t aoff[2], boff[2];
#pragma unroll
    for (int mt = 0; mt < 2; mt++)
        aoff[mt] = (uint32_t)((wm + mt * 16 + (g & 1) * 8 + lr) * 144 + (g >> 1) * 16);
#pragma unroll
    for (int p = 0; p < 2; p++)
        boff[p] = (uint32_t)((wn + p * 16 + (g >> 1) * 8 + lr) * 144 + (g & 1) * 16);

    float acc[8][4];
#pragma unroll
    for (int i = 0; i < 8; i++)
#pragma unroll
        for (int j = 0; j < 4; j++) acc[i][j] = 0.f;

    const uint32_t sbase = smem_u32(smh);

    auto load_tile = [&](int j, int st) {
        const int k0 = j * FKT;
        const uint32_t da = sbase + st * (FSTAGE * 2);
        const uint32_t db = da + HTA * 2;
#pragma unroll
        for (int i = 0; i < 4; i++) {
            int idx = tid + i * 256;
            int r = idx >> 3, c = idx & 7;
            cp_async16(da + r * 144 + c * 16, A + (size_t)(m0 + r) * DIM + k0 + c * 8);
        }
#pragma unroll
        for (int i = 0; i < 2; i++) {
            int idx = tid + i * 256;
            int r = idx >> 3, c = idx & 7;
            cp_async16(db + r * 144 + c * 16, W + (size_t)(n0 + r) * DIM + k0 + c * 8);
        }
    };

    load_tile(0, 0); cp_commit();
    load_tile(1, 1); cp_commit();

    for (int kt = 0; kt < NFKT; kt++) {
        const int s = kt % 3;
        if (kt == NFKT - 1) cp_wait<0>(); else cp_wait<1>();
        __syncthreads();
        if (kt + 2 < NFKT) {
            load_tile(kt + 2, (kt + 2) % 3);
            cp_commit();
        }

        const uint32_t aB = sbase + s * (FSTAGE * 2);
        const uint32_t bB = aB + HTA * 2;
#pragma unroll
        for (int ks = 0; ks < 4; ks++) {
            const uint32_t kb = ks * 32;
            uint32_t a[2][4], b[2][4];
            ldsm_x4(a[0], aB + aoff[0] + kb);
            ldsm_x4(a[1], aB + aoff[1] + kb);
            ldsm_x4(b[0], bB + boff[0] + kb);
            ldsm_x4(b[1], bB + boff[1] + kb);
#pragma unroll
            for (int mt = 0; mt < 2; mt++) {
                mma_f16(acc[mt * 4 + 0], a[mt], &b[0][0]);
                mma_f16(acc[mt * 4 + 1], a[mt], &b[0][2]);
                mma_f16(acc[mt * 4 + 2], a[mt], &b[1][0]);
                mma_f16(acc[mt * 4 + 3], a[mt], &b[1][2]);
            }
        }
    }

    // epilogue: vectorized stores (col pairs are adjacent; 8-wide n-tiles
    // never straddle the 48-col head boundary since 48 % 8 == 0)
#pragma unroll
    for (int mt = 0; mt < 2; mt++) {
#pragma unroll
        for (int nt = 0; nt < 4; nt++) {
            const float* d = acc[mt * 4 + nt];
            int r0 = m0 + wm + mt * 16 + grp;
            int c0 = n0 + wn + nt * 8 + tig * 2;
            float b0 = bias[c0], b1 = bias[c0 + 1];
            float v00 = d[0] + b0, v01 = d[1] + b1;   // row r0
            float v10 = d[2] + b0, v11 = d[3] + b1;   // row r0+8
            if (out_mode == 0) {
                *(float2*)&Cout[(size_t)r0 * DIM + c0]       = make_float2(v00, v01);
                *(float2*)&Cout[(size_t)(r0 + 8) * DIM + c0] = make_float2(v10, v11);
            } else {
                int h = c0 / HDIM;
                int dd = c0 - h * HDIM;
#pragma unroll
                for (int e = 0; e < 2; e++) {
                    int row = r0 + e * 8;
                    float va = e ? v10 : v00;
                    float vb = e ? v11 : v01;
                    int b2 = row >> 11;
                    int s2 = row & 2047;
                    size_t bh = (size_t)b2 * HEADS + h;
                    if (out_mode == 1) {
                        *(uint32_t*)&g_q[(bh * SEQ + s2) * HDIM + dd] =
                            pack_h2(va * QSCALE, vb * QSCALE);
                    } else if (out_mode == 2) {
                        *(uint32_t*)&g_k[(bh * SEQ + s2) * HDIM + dd] =
                            pack_h2(va, vb);
                    } else {
                        g_vt[(bh * HDIM + dd) * SEQ + s2]     = __float2half(va);
                        g_vt[(bh * HDIM + dd + 1) * SEQ + s2] = __float2half(vb);
                    }
                }
            }
        }
    }
}

// ===========================================================================
// Flash attention (exact R11 champion config): S-phase fp16 accum -> direct
// exp2, PV + l fp32 accum, 3-stage KV pipeline, 128q CTA, 4 warps x 32 rows,
// 3 CTAs/SM.
// ===========================================================================
#define ABQ 128
#define ABK 64
#define NKV (SEQ / ABK)            // 32
#define AQ_BYTES   (ABQ * 112)                  // 14336
#define AK_BYTES   (ABK * 112)                  // 7168
#define AV_BYTES   (HDIM * 144)                 // 6912
#define AKV_STAGE  (AK_BYTES + AV_BYTES)        // 14080
#define ASMEM_BYTES (AQ_BYTES + 3 * AKV_STAGE)  // 56576

__global__ __launch_bounds__(128, 3)
void attn_mma()
{
    extern __shared__ char asmem[];
    const uint32_t sbase = smem_u32(asmem);

    const int qt  = blockIdx.x;
    const int bh  = blockIdx.y;
    const int tid = threadIdx.x;
    const int w    = tid >> 5;
    const int lane = tid & 31;
    const int grp = lane >> 2, tig = lane & 3;
    const int lr = lane & 7;
    const int g  = lane >> 3;

    const __half* Qg = g_q  + ((size_t)bh * SEQ + qt * ABQ) * HDIM;
    const __half* Kg = g_k  + (size_t)bh * SEQ * HDIM;
    const __half* Vg = g_vt + (size_t)bh * HDIM * SEQ;

    auto load_kv = [&](int kt, int st) {
        const char* kg = (const char*)(Kg + (size_t)kt * ABK * HDIM);
        const uint32_t kdst = sbase + AQ_BYTES + st * AKV_STAGE;
        for (int i = tid; i < 384; i += 128) {
            int r = i / 6, c = i % 6;
            cp_async16(kdst + r * 112 + c * 16, kg + r * 96 + c * 16);
        }
        const char* vg = (const char*)(Vg + kt * ABK);
        const uint32_t vdst = kdst + AK_BYTES;
        for (int i = tid; i < 384; i += 128) {
            int d = i / 8, c = i % 8;
            cp_async16(vdst + d * 144 + c * 16, vg + (size_t)d * SEQ * 2 + c * 16);
        }
    };

    {   // Q tile: 128 rows x 6 chunks
        for (int i = tid; i < 768; i += 128) {
            int r = i / 6, c = i % 6;
            cp_async16(sbase + r * 112 + c * 16, (const char*)Qg + r * 96 + c * 16);
        }
    }
    load_kv(0, 0); cp_commit();
    load_kv(1, 1); cp_commit();

    uint32_t qoff[2];
#pragma unroll
    for (int blk = 0; blk < 2; blk++)
        qoff[blk] = (uint32_t)((w * 32 + blk * 16 + (g & 1) * 8 + lr) * 112 + (g >> 1) * 16);
    uint32_t koff[4], voff[3];
#pragma unroll
    for (int j = 0; j < 4; j++)
        koff[j] = (uint32_t)((j * 16 + (g >> 1) * 8 + lr) * 112 + (g & 1) * 16);
#pragma unroll
    for (int j = 0; j < 3; j++)
        voff[j] = (uint32_t)((j * 16 + (g >> 1) * 8 + lr) * 144 + (g & 1) * 16);

    // constant B-fragment: virtual ones column
    uint32_t bones[2];
    bones[0] = bones[1] = (grp == 0) ? 0x3C003C00u : 0u;

    uint32_t qf[2][3][4];
    float o[2][6][4];
    float ol[2][4];
#pragma unroll
    for (int blk = 0; blk < 2; blk++) {
#pragma unroll
        for (int i = 0; i < 6; i++)
#pragma unroll
            for (int j = 0; j < 4; j++) o[blk][i][j] = 0.f;
#pragma unroll
        for (int j = 0; j < 4; j++) ol[blk][j] = 0.f;
    }

    for (int kt = 0; kt < NKV; kt++) {
        const int s = kt % 3;
        if (kt == NKV - 1) cp_wait<0>(); else cp_wait<1>();
        __syncthreads();
        if (kt + 2 < NKV) {
            load_kv(kt + 2, (kt + 2) % 3);
            cp_commit();
        }

        if (kt == 0) {
#pragma unroll
            for (int blk = 0; blk < 2; blk++)
#pragma unroll
                for (int ks = 0; ks < 3; ks++)
                    ldsm_x4(qf[blk][ks], sbase + qoff[blk] + ks * 32);
        }

        // ---- S = Q K^T in fp16 accumulators -> direct exp2 -> P frags ----
        uint32_t pf[2][4][4];
        const uint32_t kB = sbase + AQ_BYTES + s * AKV_STAGE;
#pragma unroll
        for (int j = 0; j < 4; j++) {
            uint32_t b[3][4];
            ldsm_x4(b[0], kB + koff[j]);
            ldsm_x4(b[1], kB + koff[j] + 32);
            ldsm_x4(b[2], kB + koff[j] + 64);
#pragma unroll
            for (int blk = 0; blk < 2; blk++) {
                uint32_t s0[2] = {0u, 0u};
                uint32_t s1[2] = {0u, 0u};
#pragma unroll
                for (int ks = 0; ks < 3; ks++) {
                    mma_f16acc(s0, qf[blk][ks], &b[ks][0]);
                    mma_f16acc(s1, qf[blk][ks], &b[ks][2]);
                }
                pf[blk][j][0] = h2ex2(s0[0]);
                pf[blk][j][1] = h2ex2(s0[1]);
                pf[blk][j][2] = h2ex2(s1[0]);
                pf[blk][j][3] = h2ex2(s1[1]);
            }
        }

        // ---- O += P V ; l += P @ ones (fp32 accum) ----
        const uint32_t vB = kB + AK_BYTES;
#pragma unroll
        for (int j = 0; j < 3; j++) {
            uint32_t b[4][4];
            ldsm_x4(b[0], vB + voff[j]);
            ldsm_x4(b[1], vB + voff[j] + 32);
            ldsm_x4(b[2], vB + voff[j] + 64);
            ldsm_x4(b[3], vB + voff[j] + 96);
#pragma unroll
            for (int blk = 0; blk < 2; blk++)
#pragma unroll
                for (int ks = 0; ks < 4; ks++) {
                    mma_f16(o[blk][2 * j],     pf[blk][ks], &b[ks][0]);
                    mma_f16(o[blk][2 * j + 1], pf[blk][ks], &b[ks][2]);
                }
        }
#pragma unroll
        for (int blk = 0; blk < 2; blk++)
#pragma unroll
            for (int ks = 0; ks < 4; ks++)
                mma_f16(ol[blk], pf[blk][ks], bones);
    }

    // ---- epilogue ----
    const int b2 = bh >> 4, h = bh & 15;
#pragma unroll
    for (int blk = 0; blk < 2; blk++) {
        float l0 = __shfl_sync(0xffffffffu, ol[blk][0], lane & 28);
        float l1 = __shfl_sync(0xffffffffu, ol[blk][2], lane & 28);
        const float i0 = 1.f / l0, i1 = 1.f / l1;
        const int r0 = qt * ABQ + w * 32 + blk * 16 + grp;
#pragma unroll
        for (int nt = 0; nt < 6; nt++) {
            int col = h * HDIM + nt * 8 + 2 * tig;
            uint32_t p0 = pack_h2(o[blk][nt][0] * i0, o[blk][nt][1] * i0);
            uint32_t p1 = pack_h2(o[blk][nt][2] * i1, o[blk][nt][3] * i1);
            *(uint32_t*)&g_attn_h[((size_t)b2 * SEQ + r0) * DIM + col] = p0;
            *(uint32_t*)&g_attn_h[((size_t)b2 * SEQ + r0 + 8) * DIM + col] = p1;
        }
    }
}

// ---------------------------------------------------------------------------
extern "C" void kernel_launch(void* const* d_in, const int* in_sizes, int n_in,
                              void* d_out, int out_size)
{
    const float* x  = (const float*)d_in[0];
    const float* Wq = (const float*)d_in[1];
    const float* bq = (const float*)d_in[2];
    const float* Wk = (const float*)d_in[3];
    const float* bk = (const float*)d_in[4];
    const float* Wv = (const float*)d_in[5];
    const float* bv = (const float*)d_in[6];
    const float* Wo = (const float*)d_in[7];
    const float* bo = (const float*)d_in[8];
    float* out = (float*)d_out;

    cudaFuncSetAttribute(gemm_h, cudaFuncAttributeMaxDynamicSharedMemorySize, FSMEM_BYTES);
    cudaFuncSetAttribute(attn_mma, cudaFuncAttributeMaxDynamicSharedMemorySize, ASMEM_BYTES);

    cvt_kernel<<<(TOT_F4 + 255) / 256, 256>>>(x, Wq, Wk, Wv, Wo);

    __half* xh = nullptr; __half* wh = nullptr; __half* ah = nullptr;
    cudaGetSymbolAddress((void**)&xh, g_xh);
    cudaGetSymbolAddress((void**)&wh, g_wh);
    cudaGetSymbolAddress((void**)&ah, g_attn_h);

    dim3 qkv_grid(36, (BATCH * SEQ) / 128);
    gemm_h<<<qkv_grid, 256, FSMEM_BYTES>>>(xh, wh, bq, bk, bv, nullptr, 1);

    dim3 agrid(SEQ / ABQ, HEADS * BATCH);  // (16, 64)
    attn_mma<<<agrid, 128, ASMEM_BYTES>>>();

    dim3 o_grid(12, (BATCH * SEQ) / 128);
    gemm_h<<<o_grid, 256, FSMEM_BYTES>>>(ah, wh + 3 * DIM * DIM, bo, nullptr, nullptr, out, 0);
}

// round 16
// speedup vs baseline: 1.0935x; 1.0065x over previous
#include <cuda_runtime.h>
#include <cuda_fp16.h>
#include <cstdint>
#include <math.h>

#define BATCH 4
#define SEQ   2048
#define DIM   768
#define HEADS 16
#define HDIM  48

// log2(e) / sqrt(48): folds softmax scale + exp2 conversion into Q
#define QSCALE 0.2082351f

// Scratch (static device globals allowed; runtime allocation is not)
__device__ __align__(128) __half g_xh[BATCH * SEQ * DIM];            // x in fp16
__device__ __align__(128) __half g_wh[4 * DIM * DIM];                // Wq,Wk,Wv,Wo fp16
__device__ __align__(128) __half g_q[BATCH * HEADS * SEQ * HDIM];    // [bh][s][d], pre-scaled
__device__ __align__(128) __half g_k[BATCH * HEADS * SEQ * HDIM];    // [bh][s][d]
__device__ __align__(128) __half g_v[BATCH * HEADS * SEQ * HDIM];    // [bh][s][d] (row-major now!)
__device__ __align__(128) __half g_attn_h[BATCH * SEQ * DIM];        // [b][s][h*48+d] fp16

// ---------------------------------------------------------------------------
__device__ __forceinline__ uint32_t smem_u32(const void* p) {
    uint32_t a;
    asm("{ .reg .u64 t; cvta.to.shared.u64 t, %1; cvt.u32.u64 %0, t; }" : "=r"(a) : "l"(p));
    return a;
}
__device__ __forceinline__ void cp_async16(uint32_t saddr, const void* gptr) {
    asm volatile("cp.async.cg.shared.global [%0], [%1], 16;" :: "r"(saddr), "l"(gptr));
}
__device__ __forceinline__ void cp_commit() { asm volatile("cp.async.commit_group;" ::: "memory"); }
template <int N>
__device__ __forceinline__ void cp_wait() { asm volatile("cp.async.wait_group %0;" :: "n"(N) : "memory"); }

__device__ __forceinline__ void mma_f16(float* d, const uint32_t* a, const uint32_t* b) {
    asm volatile(
        "mma.sync.aligned.m16n8k16.row.col.f32.f16.f16.f32 "
        "{%0,%1,%2,%3}, {%4,%5,%6,%7}, {%8,%9}, {%0,%1,%2,%3};"
        : "+f"(d[0]), "+f"(d[1]), "+f"(d[2]), "+f"(d[3])
        : "r"(a[0]), "r"(a[1]), "r"(a[2]), "r"(a[3]), "r"(b[0]), "r"(b[1]));
}
// fp16-accumulator mma: d/c are 2 x f16x2 regs
__device__ __forceinline__ void mma_f16acc(uint32_t* d, const uint32_t* a, const uint32_t* b) {
    asm volatile(
        "mma.sync.aligned.m16n8k16.row.col.f16.f16.f16.f16 "
        "{%0,%1}, {%2,%3,%4,%5}, {%6,%7}, {%0,%1};"
        : "+r"(d[0]), "+r"(d[1])
        : "r"(a[0]), "r"(a[1]), "r"(a[2]), "r"(a[3]), "r"(b[0]), "r"(b[1]));
}
__device__ __forceinline__ void ldsm_x4(uint32_t* r, uint32_t addr) {
    asm volatile("ldmatrix.sync.aligned.m8n8.x4.shared.b16 {%0,%1,%2,%3}, [%4];"
        : "=r"(r[0]), "=r"(r[1]), "=r"(r[2]), "=r"(r[3]) : "r"(addr));
}
__device__ __forceinline__ void ldsm_x4_t(uint32_t* r, uint32_t addr) {
    asm volatile("ldmatrix.sync.aligned.m8n8.x4.trans.shared.b16 {%0,%1,%2,%3}, [%4];"
        : "=r"(r[0]), "=r"(r[1]), "=r"(r[2]), "=r"(r[3]) : "r"(addr));
}
__device__ __forceinline__ uint32_t pack_h2(float lo, float hi) {
    uint32_t r; asm("cvt.rn.f16x2.f32 %0, %1, %2;" : "=r"(r) : "f"(hi), "f"(lo)); return r;
}
__device__ __forceinline__ uint32_t h2ex2(uint32_t x) {
    uint32_t r; asm("ex2.approx.f16x2 %0, %1;" : "=r"(r) : "r"(x)); return r;
}

// ===========================================================================
// fp32 -> fp16 conversion of x and the 4 weight matrices (one pass)
// ===========================================================================
#define X_F4   ((BATCH * SEQ * DIM) / 4)
#define W_F4   ((DIM * DIM) / 4)
#define TOT_F4 (X_F4 + 4 * W_F4)

__global__ __launch_bounds__(256)
void cvt_kernel(const float* __restrict__ x,  const float* __restrict__ wq,
                const float* __restrict__ wk, const float* __restrict__ wv,
                const float* __restrict__ wo)
{
    size_t i = (size_t)blockIdx.x * blockDim.x + threadIdx.x;
    if (i >= TOT_F4) return;
    const float* src;
    __half* dst;
    size_t off;
    if (i < X_F4) {
        src = x; dst = g_xh; off = i;
    } else {
        size_t j = i - X_F4;
        int w = (int)(j / W_F4);
        off = j % W_F4;
        src = (w == 0) ? wq : (w == 1) ? wk : (w == 2) ? wv : wo;
        dst = g_wh + (size_t)w * (DIM * DIM);
    }
    float4 v = ((const float4*)src)[off];
    __half2* d2 = (__half2*)(dst + off * 4);
    d2[0] = __floats2half2_rn(v.x, v.y);
    d2[1] = __floats2half2_rn(v.z, v.w);
}

// ===========================================================================
// fp16 mma.sync GEMM (R15 champion config): 128x64 CTA, 256 thr, 2 CTAs/SM,
// 3-stage cp.async pipeline, one barrier per k-iter. Vectorized epilogue.
// All head-scatter outputs (q/k/v) are now row-major [bh][s][d] fp16x2 stores.
// ===========================================================================
#define FKT 64
#define NFKT (DIM / FKT)           // 12
#define FST 72                     // halves per row (144 B)
#define HTA (128 * FST)
#define HTB (64 * FST)
#define FSTAGE (HTA + HTB)
#define FSMEM_BYTES (3 * FSTAGE * 2)   // 82944 B

__global__ __launch_bounds__(256, 2)
void gemm_h(const __half* __restrict__ A, const __half* __restrict__ Wbase,
            const float* __restrict__ bias0, const float* __restrict__ bias1,
            const float* __restrict__ bias2, float* __restrict__ Cout, int fused)
{
    extern __shared__ __half smh[];

    int widx, n0, out_mode;
    const __half* W;
    const float* bias;
    if (fused) {
        widx = blockIdx.x / 12;
        n0 = (blockIdx.x % 12) * 64;
        W = Wbase + (size_t)widx * (DIM * DIM);
        bias = (widx == 0) ? bias0 : (widx == 1) ? bias1 : bias2;
        out_mode = 1 + widx;
    } else {
        n0 = blockIdx.x * 64;
        W = Wbase;
        bias = bias0;
        out_mode = 0;
    }
    const int m0 = blockIdx.y * 128;

    const int tid  = threadIdx.x;
    const int wi   = tid >> 5;
    const int lane = tid & 31;
    const int wm = (wi & 3) * 32;
    const int wn = (wi >> 2) * 32;
    const int grp = lane >> 2;
    const int tig = lane & 3;
    const int lr = lane & 7;
    const int g  = lane >> 3;

    uint32_t aoff[2], boff[2];
#pragma unroll
    for (int mt = 0; mt < 2; mt++)
        aoff[mt] = (uint32_t)((wm + mt * 16 + (g & 1) * 8 + lr) * 144 + (g >> 1) * 16);
#pragma unroll
    for (int p = 0; p < 2; p++)
        boff[p] = (uint32_t)((wn + p * 16 + (g >> 1) * 8 + lr) * 144 + (g & 1) * 16);

    float acc[8][4];
#pragma unroll
    for (int i = 0; i < 8; i++)
#pragma unroll
        for (int j = 0; j < 4; j++) acc[i][j] = 0.f;

    const uint32_t sbase = smem_u32(smh);

    auto load_tile = [&](int j, int st) {
        const int k0 = j * FKT;
        const uint32_t da = sbase + st * (FSTAGE * 2);
        const uint32_t db = da + HTA * 2;
#pragma unroll
        for (int i = 0; i < 4; i++) {
            int idx = tid + i * 256;
            int r = idx >> 3, c = idx & 7;
            cp_async16(da + r * 144 + c * 16, A + (size_t)(m0 + r) * DIM + k0 + c * 8);
        }
#pragma unroll
        for (int i = 0; i < 2; i++) {
            int idx = tid + i * 256;
            int r = idx >> 3, c = idx & 7;
            cp_async16(db + r * 144 + c * 16, W + (size_t)(n0 + r) * DIM + k0 + c * 8);
        }
    };

    load_tile(0, 0); cp_commit();
    load_tile(1, 1); cp_commit();

    for (int kt = 0; kt < NFKT; kt++) {
        const int s = kt % 3;
        if (kt == NFKT - 1) cp_wait<0>(); else cp_wait<1>();
        __syncthreads();
        if (kt + 2 < NFKT) {
            load_tile(kt + 2, (kt + 2) % 3);
            cp_commit();
        }

        const uint32_t aB = sbase + s * (FSTAGE * 2);
        const uint32_t bB = aB + HTA * 2;
#pragma unroll
        for (int ks = 0; ks < 4; ks++) {
            const uint32_t kb = ks * 32;
            uint32_t a[2][4], b[2][4];
            ldsm_x4(a[0], aB + aoff[0] + kb);
            ldsm_x4(a[1], aB + aoff[1] + kb);
            ldsm_x4(b[0], bB + boff[0] + kb);
            ldsm_x4(b[1], bB + boff[1] + kb);
#pragma unroll
            for (int mt = 0; mt < 2; mt++) {
                mma_f16(acc[mt * 4 + 0], a[mt], &b[0][0]);
                mma_f16(acc[mt * 4 + 1], a[mt], &b[0][2]);
                mma_f16(acc[mt * 4 + 2], a[mt], &b[1][0]);
                mma_f16(acc[mt * 4 + 3], a[mt], &b[1][2]);
            }
        }
    }

    // epilogue: vectorized stores; q/k/v all row-major [bh][s][d]
#pragma unroll
    for (int mt = 0; mt < 2; mt++) {
#pragma unroll
        for (int nt = 0; nt < 4; nt++) {
            const float* d = acc[mt * 4 + nt];
            int r0 = m0 + wm + mt * 16 + grp;
            int c0 = n0 + wn + nt * 8 + tig * 2;
            float b0 = bias[c0], b1 = bias[c0 + 1];
            float v00 = d[0] + b0, v01 = d[1] + b1;   // row r0
            float v10 = d[2] + b0, v11 = d[3] + b1;   // row r0+8
            if (out_mode == 0) {
                *(float2*)&Cout[(size_t)r0 * DIM + c0]       = make_float2(v00, v01);
                *(float2*)&Cout[(size_t)(r0 + 8) * DIM + c0] = make_float2(v10, v11);
            } else {
                int h = c0 / HDIM;
                int dd = c0 - h * HDIM;
                __half* dst = (out_mode == 1) ? g_q : (out_mode == 2) ? g_k : g_v;
                float sc = (out_mode == 1) ? QSCALE : 1.0f;
#pragma unroll
                for (int e = 0; e < 2; e++) {
                    int row = r0 + e * 8;
                    float va = e ? v10 : v00;
                    float vb = e ? v11 : v01;
                    int b2 = row >> 11;
                    int s2 = row & 2047;
                    size_t bh = (size_t)b2 * HEADS + h;
                    *(uint32_t*)&dst[(bh * SEQ + s2) * HDIM + dd] =
                        pack_h2(va * sc, vb * sc);
                }
            }
        }
    }
}

// ===========================================================================
// Flash attention: S-phase fp16 accum -> direct exp2, PV + l fp32 accum,
// 3-stage KV pipeline, 128q CTA, 4 warps x 32 rows, 3 CTAs/SM.
// V is row-major [s][d] in smem; B-fragments come from ldmatrix.trans.
// ===========================================================================
#define ABQ 128
#define ABK 64
#define NKV (SEQ / ABK)            // 32
#define AQ_BYTES   (ABQ * 112)                  // 14336
#define AK_BYTES   (ABK * 112)                  // 7168
#define AV_BYTES   (ABK * 112)                  // 7168 (row-major V tile)
#define AKV_STAGE  (AK_BYTES + AV_BYTES)        // 14336
#define ASMEM_BYTES (AQ_BYTES + 3 * AKV_STAGE)  // 57344

__global__ __launch_bounds__(128, 3)
void attn_mma()
{
    extern __shared__ char asmem[];
    const uint32_t sbase = smem_u32(asmem);

    const int qt  = blockIdx.x;
    const int bh  = blockIdx.y;
    const int tid = threadIdx.x;
    const int w    = tid >> 5;
    const int lane = tid & 31;
    const int grp = lane >> 2, tig = lane & 3;
    const int lr = lane & 7;
    const int g  = lane >> 3;

    const __half* Qg = g_q + ((size_t)bh * SEQ + qt * ABQ) * HDIM;
    const __half* Kg = g_k + (size_t)bh * SEQ * HDIM;
    const __half* Vg = g_v + (size_t)bh * SEQ * HDIM;

    auto load_kv = [&](int kt, int st) {
        const char* kg = (const char*)(Kg + (size_t)kt * ABK * HDIM);
        const char* vg = (const char*)(Vg + (size_t)kt * ABK * HDIM);
        const uint32_t kdst = sbase + AQ_BYTES + st * AKV_STAGE;
        const uint32_t vdst = kdst + AK_BYTES;
        for (int i = tid; i < 384; i += 128) {           // 64 rows x 6 chunks
            int r = i / 6, c = i % 6;
            cp_async16(kdst + r * 112 + c * 16, kg + r * 96 + c * 16);
            cp_async16(vdst + r * 112 + c * 16, vg + r * 96 + c * 16);
        }
    };

    {   // Q tile: 128 rows x 6 chunks
        for (int i = tid; i < 768; i += 128) {
            int r = i / 6, c = i % 6;
            cp_async16(sbase + r * 112 + c * 16, (const char*)Qg + r * 96 + c * 16);
        }
    }
    load_kv(0, 0); cp_commit();
    load_kv(1, 1); cp_commit();

    uint32_t qoff[2];
#pragma unroll
    for (int blk = 0; blk < 2; blk++)
        qoff[blk] = (uint32_t)((w * 32 + blk * 16 + (g & 1) * 8 + lr) * 112 + (g >> 1) * 16);
    uint32_t koff[4];
#pragma unroll
    for (int j = 0; j < 4; j++)
        koff[j] = (uint32_t)((j * 16 + (g >> 1) * 8 + lr) * 112 + (g & 1) * 16);
    // V trans-ldsm base: row = s (k-dim), col = d (n-dim)
    // m0: (s0-7, d0-7)  m1: (s8-15, d0-7)  m2: (s0-7, d8-15)  m3: (s8-15, d8-15)
    const uint32_t vbase = (uint32_t)(((g & 1) * 8 + lr) * 112 + (g >> 1) * 16);

    // constant B-fragment: virtual ones column
    uint32_t bones[2];
    bones[0] = bones[1] = (grp == 0) ? 0x3C003C00u : 0u;

    uint32_t qf[2][3][4];
    float o[2][6][4];
    float ol[2][4];
#pragma unroll
    for (int blk = 0; blk < 2; blk++) {
#pragma unroll
        for (int i = 0; i < 6; i++)
#pragma unroll
            for (int j = 0; j < 4; j++) o[blk][i][j] = 0.f;
#pragma unroll
        for (int j = 0; j < 4; j++) ol[blk][j] = 0.f;
    }

    for (int kt = 0; kt < NKV; kt++) {
        const int s = kt % 3;
        if (kt == NKV - 1) cp_wait<0>(); else cp_wait<1>();
        __syncthreads();
        if (kt + 2 < NKV) {
            load_kv(kt + 2, (kt + 2) % 3);
            cp_commit();
        }

        if (kt == 0) {
#pragma unroll
            for (int blk = 0; blk < 2; blk++)
#pragma unroll
                for (int ks = 0; ks < 3; ks++)
                    ldsm_x4(qf[blk][ks], sbase + qoff[blk] + ks * 32);
        }

        // ---- S = Q K^T in fp16 accumulators -> direct exp2 -> P frags ----
        uint32_t pf[2][4][4];
        const uint32_t kB = sbase + AQ_BYTES + s * AKV_STAGE;
#pragma unroll
        for (int j = 0; j < 4; j++) {
            uint32_t b[3][4];
            ldsm_x4(b[0], kB + koff[j]);
            ldsm_x4(b[1], kB + koff[j] + 32);
            ldsm_x4(b[2], kB + koff[j] + 64);
#pragma unroll
            for (int blk = 0; blk < 2; blk++) {
                uint32_t s0[2] = {0u, 0u};
                uint32_t s1[2] = {0u, 0u};
#pragma unroll
                for (int ks = 0; ks < 3; ks++) {
                    mma_f16acc(s0, qf[blk][ks], &b[ks][0]);
                    mma_f16acc(s1, qf[blk][ks], &b[ks][2]);
                }
                pf[blk][j][0] = h2ex2(s0[0]);
                pf[blk][j][1] = h2ex2(s0[1]);
                pf[blk][j][2] = h2ex2(s1[0]);
                pf[blk][j][3] = h2ex2(s1[1]);
            }
        }

        // ---- O += P V ; l += P @ ones (fp32 accum) ----
        const uint32_t vB = kB + AK_BYTES;
#pragma unroll
        for (int j = 0; j < 3; j++) {       // j = d-chunk of 16 (nt pair)
            uint32_t b[4][4];
#pragma unroll
            for (int ks = 0; ks < 4; ks++)  // ks = s-chunk of 16
                ldsm_x4_t(b[ks], vB + vbase + ks * (16 * 112) + j * 32);
#pragma unroll
            for (int blk = 0; blk < 2; blk++)
#pragma unroll
                for (int ks = 0; ks < 4; ks++) {
                    mma_f16(o[blk][2 * j],     pf[blk][ks], &b[ks][0]);
                    mma_f16(o[blk][2 * j + 1], pf[blk][ks], &b[ks][2]);
                }
        }
#pragma unroll
        for (int blk = 0; blk < 2; blk++)
#pragma unroll
            for (int ks = 0; ks < 4; ks++)
                mma_f16(ol[blk], pf[blk][ks], bones);
    }

    // ---- epilogue ----
    const int b2 = bh >> 4, h = bh & 15;
#pragma unroll
    for (int blk = 0; blk < 2; blk++) {
        float l0 = __shfl_sync(0xffffffffu, ol[blk][0], lane & 28);
        float l1 = __shfl_sync(0xffffffffu, ol[blk][2], lane & 28);
        const float i0 = 1.f / l0, i1 = 1.f / l1;
        const int r0 = qt * ABQ + w * 32 + blk * 16 + grp;
#pragma unroll
        for (int nt = 0; nt < 6; nt++) {
            int col = h * HDIM + nt * 8 + 2 * tig;
            uint32_t p0 = pack_h2(o[blk][nt][0] * i0, o[blk][nt][1] * i0);
            uint32_t p1 = pack_h2(o[blk][nt][2] * i1, o[blk][nt][3] * i1);
            *(uint32_t*)&g_attn_h[((size_t)b2 * SEQ + r0) * DIM + col] = p0;
            *(uint32_t*)&g_attn_h[((size_t)b2 * SEQ + r0 + 8) * DIM + col] = p1;
        }
    }
}

// ---------------------------------------------------------------------------
extern "C" void kernel_launch(void* const* d_in, const int* in_sizes, int n_in,
                              void* d_out, int out_size)
{
    const float* x  = (const float*)d_in[0];
    const float* Wq = (const float*)d_in[1];
    const float* bq = (const float*)d_in[2];
    const float* Wk = (const float*)d_in[3];
    const float* bk = (const float*)d_in[4];
    const float* Wv = (const float*)d_in[5];
    const float* bv = (const float*)d_in[6];
    const float* Wo = (const float*)d_in[7];
    const float* bo = (const float*)d_in[8];
    float* out = (float*)d_out;

    cudaFuncSetAttribute(gemm_h, cudaFuncAttributeMaxDynamicSharedMemorySize, FSMEM_BYTES);
    cudaFuncSetAttribute(attn_mma, cudaFuncAttributeMaxDynamicSharedMemorySize, ASMEM_BYTES);

    cvt_kernel<<<(TOT_F4 + 255) / 256, 256>>>(x, Wq, Wk, Wv, Wo);

    __half* xh = nullptr; __half* wh = nullptr; __half* ah = nullptr;
    cudaGetSymbolAddress((void**)&xh, g_xh);
    cudaGetSymbolAddress((void**)&wh, g_wh);
    cudaGetSymbolAddress((void**)&ah, g_attn_h);

    dim3 qkv_grid(36, (BATCH * SEQ) / 128);
    gemm_h<<<qkv_grid, 256, FSMEM_BYTES>>>(xh, wh, bq, bk, bv, nullptr, 1);

    dim3 agrid(SEQ / ABQ, HEADS * BATCH);  // (16, 64)
    attn_mma<<<agrid, 128, ASMEM_BYTES>>>();

    dim3 o_grid(12, (BATCH * SEQ) / 128);
    gemm_h<<<o_grid, 256, FSMEM_BYTES>>>(ah, wh + 3 * DIM * DIM, bo, nullptr, nullptr, out, 0);
}